// round 13
// baseline (speedup 1.0000x reference)
#include <cuda_runtime.h>

#define THREADS 224   // 7 warps; threads 0..195 = 98 patch-pairs x 2 sub-threads
#define NWARPS 7

typedef unsigned long long u64;

// ---- packed f32x2 primitives (sm_103a FFMA2 path) ----
__device__ __forceinline__ u64 pk2(float lo, float hi) {
    u64 r;
    asm("mov.b64 %0, {%1, %2};" : "=l"(r)
        : "r"(__float_as_uint(lo)), "r"(__float_as_uint(hi)));
    return r;
}
__device__ __forceinline__ void upk2(float& lo, float& hi, u64 v) {
    unsigned a, b;
    asm("mov.b64 {%0, %1}, %2;" : "=r"(a), "=r"(b) : "l"(v));
    lo = __uint_as_float(a); hi = __uint_as_float(b);
}
__device__ __forceinline__ u64 fma2_(u64 a, u64 b, u64 c) {
    u64 d;
    asm("fma.rn.f32x2 %0, %1, %2, %3;" : "=l"(d) : "l"(a), "l"(b), "l"(c));
    return d;
}
__device__ __forceinline__ u64 mul2_(u64 a, u64 b) {
    u64 d;
    asm("mul.rn.f32x2 %0, %1, %2;" : "=l"(d) : "l"(a), "l"(b));
    return d;
}

// Generic packed butterfly with 12 packed coeffs
// c = [pp qq nqq rr ss nss tt uu nuu vv ww nww]:
//   reA' = p*rA - q*iA + r*rB - s*iB      imA' = p*iA + q*rA + r*iB + s*rB
//   reB' = t*rA - u*iA + v*rB - w*iB      imB' = t*iA + u*rA + v*iB + w*rB
__device__ __forceinline__ void bfly12(u64& rA, u64& iA, u64& rB, u64& iB,
                                       const u64* c, bool swap_out) {
    u64 nrA = fma2_(c[5],  iB, fma2_(c[3], rB, fma2_(c[2], iA, mul2_(c[0], rA))));
    u64 niA = fma2_(c[4],  rB, fma2_(c[3], iB, fma2_(c[1], rA, mul2_(c[0], iA))));
    u64 nrB = fma2_(c[11], iB, fma2_(c[9], rB, fma2_(c[8], iA, mul2_(c[6], rA))));
    u64 niB = fma2_(c[10], rB, fma2_(c[9], iB, fma2_(c[7], rA, mul2_(c[6], iA))));
    if (swap_out) { rA = nrB; iA = niB; rB = nrA; iB = niA; }
    else          { rA = nrA; iA = niA; rB = nrB; iB = niB; }
}

__global__ __launch_bounds__(THREADS, 1)
void qnet_kernel(const float* __restrict__ x,       // [B,1,28,28]
                 const float* __restrict__ weight,  // [60]
                 const float* __restrict__ fc1_w,   // [64,784]
                 const float* __restrict__ fc1_b,   // [64]
                 const float* __restrict__ fc2_w,   // [10,64]
                 const float* __restrict__ fc2_b,   // [10]
                 float* __restrict__ out)           // [B,10]
{
    __shared__ __align__(16) float feat[784];
    __shared__ float  hidden[64];
    __shared__ float4 g[20];          // fused Ry*Rz*Ry per (layer,qubit)
    __shared__ u64 cG0[4][2][12];     // packed G0' coeffs, per layer 1..4, per sub
    __shared__ u64 cG1[4][12];        // packed G1 coeffs (sub-independent)
    __shared__ u64 cG3[4][2][6];      // packed split-q3 coeffs [P Q nQ R S nS]

    const int b   = blockIdx.x;
    const int tid = threadIdx.x;

    // ---- Stage 1: fused SU(2) gates U = Ry(p2)*Rz(p1)*Ry(p0)
    if (tid < 20) {
        const int L = tid >> 2, q = tid & 3;
        const float* p = weight + 12 * L;
        float ca, sa, cb, sb, cc, sc;
        sincosf(0.5f * p[q],     &sa, &ca);
        sincosf(0.5f * p[4 + q], &sb, &cb);
        sincosf(0.5f * p[8 + q], &sc, &cc);
        float t0 = cc * ca - sc * sa;
        float t1 = cc * ca + sc * sa;
        float t2 = cc * sa + sc * ca;
        float t3 = cc * sa - sc * ca;
        g[tid] = make_float4(cb * t0, -sb * t1, -cb * t2, sb * t3);
    }
    __syncthreads();

    // ---- Stage 2: packed coefficient banks (both sub variants)
    if (tid < 8) {
        const int li = tid >> 1, s = tid & 1;   // layer = li+1
        // G0': X30 pre-fold = column swap for sub=1
        float4 G = g[(li + 1) * 4 + 0];
        float a = G.x, bb = G.y, c = G.z, d = G.w;
        float p_, q_, r_, s_, t_, u_, v_, w_;
        if (s == 0) { p_ = a; q_ = bb; r_ = c;  s_ = d;  t_ = -c; u_ = d;   v_ = a;  w_ = -bb; }
        else        { p_ = c; q_ = d;  r_ = a;  s_ = bb; t_ = a;  u_ = -bb; v_ = -c; w_ = d; }
        u64* o = cG0[li][s];
        o[0] = pk2(p_, p_);  o[1]  = pk2(q_, q_);  o[2]  = pk2(-q_, -q_);
        o[3] = pk2(r_, r_);  o[4]  = pk2(s_, s_);  o[5]  = pk2(-s_, -s_);
        o[6] = pk2(t_, t_);  o[7]  = pk2(u_, u_);  o[8]  = pk2(-u_, -u_);
        o[9] = pk2(v_, v_);  o[10] = pk2(w_, w_);  o[11] = pk2(-w_, -w_);
        // G3': X23 post-fold = opposite-row coeffs on odd amplitudes (lane hi)
        G = g[(li + 1) * 4 + 3];
        a = G.x; bb = G.y; c = G.z; d = G.w;
        const bool rs = (li + 1) < 4;
        float Pe = a, Qe = s ? -bb : bb, Re_ = s ? -c : c, Se = d;
        float Po, Qo, Ro, So;
        if (rs) { Po = s ? c : -c; Qo = d; Ro = a; So = s ? bb : -bb; }
        else    { Po = Pe; Qo = Qe; Ro = Re_; So = Se; }
        u64* o3 = cG3[li][s];
        o3[0] = pk2(Pe, Po);   o3[1] = pk2(Qe, Qo);   o3[2] = pk2(-Qe, -Qo);
        o3[3] = pk2(Re_, Ro);  o3[4] = pk2(Se, So);   o3[5] = pk2(-Se, -So);
    } else if (tid < 12) {
        const int li = tid - 8;
        float4 G = g[(li + 1) * 4 + 1];
        float a = G.x, bb = G.y, c = G.z, d = G.w;
        u64* o = cG1[li];
        o[0] = pk2(a, a);    o[1]  = pk2(bb, bb);  o[2]  = pk2(-bb, -bb);
        o[3] = pk2(c, c);    o[4]  = pk2(d, d);    o[5]  = pk2(-d, -d);
        o[6] = pk2(-c, -c);  o[7]  = pk2(d, d);    o[8]  = pk2(-d, -d);
        o[9] = pk2(a, a);    o[10] = pk2(-bb, -bb); o[11] = pk2(bb, bb);
    }
    __syncthreads();

    // ---- Circuit: each thread = one q3-sub of TWO patches (pair, pair+98).
    // State per patch: 8 amps m=(b0<<2)|(b1<<1)|b2, packed along b2:
    // zr[s][k] = (re[2k], re[2k+1]), k=(b0<<1)|b1, s = patch slot.
    {
        const int pair  = tid >> 1;
        const bool valid = pair < 98;
        const int pA  = valid ? pair : 97;
        const int pB  = pA + 98;
        const int sub = tid & 1;                 // qubit-3 bit

        const float PI = 3.14159265358979323846f;
        u64 zr[2][4], zi[2][4];

        const int pidx[2] = { pA, pB };
#pragma unroll
        for (int s = 0; s < 2; s++) {
            const int pp = pidx[s];
            const int pi_ = pp / 14, pj = pp % 14;
            const float* xb = x + b * 784 + (2 * pi_) * 28 + 2 * pj;
            const float2 xr0 = *reinterpret_cast<const float2*>(xb);
            const float2 xr1 = *reinterpret_cast<const float2*>(xb + 28);
            const float ang[4] = { xr0.x, xr0.y, xr1.x, xr1.y };

            // Layer 0 fused with Rx encoding on |0000>, ring-0 folded via
            // twisted indexing: state[m] = A(b0)*B(b0^b1)*C(b1^b2)*D(b2^sub)
            float R0[4], I0[4], R1[4], I1[4];
#pragma unroll
            for (int q = 0; q < 4; q++) {
                float sx, cx;
                __sincosf(PI * ang[q], &sx, &cx);
                float4 G = g[q];
                R0[q] =  G.x * cx + G.w * sx;
                I0[q] =  G.y * cx - G.z * sx;
                R1[q] = -(G.z * cx + G.y * sx);
                I1[q] =  G.w * cx - G.x * sx;
            }

            float re[8], im[8];
            float Dr[2], Di[2];
            Dr[0] = sub ? R1[3] : R0[3];  Di[0] = sub ? I1[3] : I0[3];
            Dr[1] = sub ? R0[3] : R1[3];  Di[1] = sub ? I0[3] : I1[3];
#pragma unroll
            for (int b0 = 0; b0 < 2; b0++) {
                float ar = b0 ? R1[0] : R0[0], ai = b0 ? I1[0] : I0[0];
#pragma unroll
                for (int b1 = 0; b1 < 2; b1++) {
                    int ib = b0 ^ b1;
                    float br = ib ? R1[1] : R0[1], bi = ib ? I1[1] : I0[1];
                    float abr = ar * br - ai * bi;
                    float abi = ar * bi + ai * br;
#pragma unroll
                    for (int b2 = 0; b2 < 2; b2++) {
                        int ic = b1 ^ b2;
                        float cr = ic ? R1[2] : R0[2], ci = ic ? I1[2] : I0[2];
                        float tr = abr * cr - abi * ci;
                        float ti = abr * ci + abi * cr;
                        int m = b0 * 4 + b1 * 2 + b2;
                        re[m] = tr * Dr[b2] - ti * Di[b2];
                        im[m] = tr * Di[b2] + ti * Dr[b2];
                    }
                }
            }
#pragma unroll
            for (int k = 0; k < 4; k++) {
                zr[s][k] = pk2(re[2 * k], re[2 * k + 1]);
                zi[s][k] = pk2(im[2 * k], im[2 * k + 1]);
            }
        }

        // ---- Blocks 1..4 (ring folds in coefficients; both patches per gate
        // so the two independent chains interleave in the issue stream)
#pragma unroll
        for (int layer = 1; layer < 5; layer++) {
            const int li = layer - 1;
            const bool rs = (layer < 4);

            // G0' on q0: groups (k0,k2),(k1,k3); no row swap
            {
                const u64* c = cG0[li][sub];
#pragma unroll
                for (int s = 0; s < 2; s++) {
                    bfly12(zr[s][0], zi[s][0], zr[s][2], zi[s][2], c, false);
                    bfly12(zr[s][1], zi[s][1], zr[s][3], zi[s][3], c, false);
                }
            }
            // G1' on q1: groups (k0,k1),(k2,k3); X01 fold: row-swap on (k2,k3)
            {
                const u64* c = cG1[li];
#pragma unroll
                for (int s = 0; s < 2; s++) {
                    bfly12(zr[s][0], zi[s][0], zr[s][1], zi[s][1], c, false);
                    bfly12(zr[s][2], zi[s][2], zr[s][3], zi[s][3], c, rs);
                }
            }
            // G2' on q2 (intra-register): scalar; X12 fold: row-swap on k&1
            {
                float4 G = g[layer * 4 + 2];
                float a = G.x, bb = G.y, c = G.z, d = G.w;
#pragma unroll
                for (int s = 0; s < 2; s++) {
#pragma unroll
                    for (int k = 0; k < 4; k++) {
                        float r0, r1, i0, i1;
                        upk2(r0, r1, zr[s][k]);
                        upk2(i0, i1, zi[s][k]);
                        float n0r =  a * r0 - bb * i0 + c * r1 - d * i1;
                        float n0i =  a * i0 + bb * r0 + c * i1 + d * r1;
                        float n1r = -c * r0 - d * i0 + a * r1 + bb * i1;
                        float n1i = -c * i0 + d * r0 + a * i1 - bb * r1;
                        if (rs && (k & 1)) { zr[s][k] = pk2(n1r, n0r); zi[s][k] = pk2(n1i, n0i); }
                        else               { zr[s][k] = pk2(n0r, n1r); zi[s][k] = pk2(n0i, n1i); }
                    }
                }
            }
            // G3' on split q3: partner exchange + packed parity coefficients
            {
                const u64* c3 = cG3[li][sub];
#pragma unroll
                for (int s = 0; s < 2; s++) {
#pragma unroll
                    for (int k = 0; k < 4; k++) {
                        u64 pr = __shfl_xor_sync(0xffffffffu, zr[s][k], 1);
                        u64 pi = __shfl_xor_sync(0xffffffffu, zi[s][k], 1);
                        u64 nr = fma2_(c3[5], pi, fma2_(c3[3], pr, fma2_(c3[2], zi[s][k], mul2_(c3[0], zr[s][k]))));
                        u64 ni = fma2_(c3[4], pr, fma2_(c3[3], pi, fma2_(c3[1], zr[s][k], mul2_(c3[0], zi[s][k]))));
                        zr[s][k] = nr; zi[s][k] = ni;
                    }
                }
            }
        }

        // ---- <Z_q> partials (packed square), combine with partner
#pragma unroll
        for (int s = 0; s < 2; s++) {
            float pe[4], po[4];
#pragma unroll
            for (int k = 0; k < 4; k++) {
                u64 s2 = fma2_(zr[s][k], zr[s][k], mul2_(zi[s][k], zi[s][k]));
                upk2(pe[k], po[k], s2);
            }
            float e0 = (pe[0] + po[0]) + (pe[1] + po[1]) - (pe[2] + po[2]) - (pe[3] + po[3]);
            float e1 = (pe[0] + po[0]) - (pe[1] + po[1]) + (pe[2] + po[2]) - (pe[3] + po[3]);
            float e2 = (pe[0] - po[0]) + (pe[1] - po[1]) + (pe[2] - po[2]) + (pe[3] - po[3]);
            float et = (pe[0] + po[0]) + (pe[1] + po[1]) + (pe[2] + po[2]) + (pe[3] + po[3]);
            float e3 = sub ? -et : et;

            e0 += __shfl_xor_sync(0xffffffffu, e0, 1);
            e1 += __shfl_xor_sync(0xffffffffu, e1, 1);
            e2 += __shfl_xor_sync(0xffffffffu, e2, 1);
            e3 += __shfl_xor_sync(0xffffffffu, e3, 1);

            if (valid && sub == 0) {
                const int pp = pidx[s];
                feat[pp * 4 + 0] = e0;
                feat[pp * 4 + 1] = e1;
                feat[pp * 4 + 2] = e2;
                feat[pp * 4 + 3] = e3;
            }
        }
    }
    __syncthreads();

    // ---- FC1 (packed): hidden[h] = relu(feat . fc1_w[h,:] + fc1_b[h])
    {
        const int warp = tid >> 5;
        const int lane = tid & 31;
        const u64* F2 = reinterpret_cast<const u64*>(feat);
        for (int h = warp; h < 64; h += NWARPS) {
            u64 acc2 = 0ull;    // packed (+0,+0)
            for (int kk = lane; kk < 196; kk += 32) {
                const ulonglong2 wv =
                    *reinterpret_cast<const ulonglong2*>(fc1_w + (h * 196 + kk) * 4);
                acc2 = fma2_(wv.x, F2[2 * kk],     acc2);
                acc2 = fma2_(wv.y, F2[2 * kk + 1], acc2);
            }
            float alo, ahi;
            upk2(alo, ahi, acc2);
            float acc = alo + ahi;
#pragma unroll
            for (int off = 16; off; off >>= 1)
                acc += __shfl_down_sync(0xffffffffu, acc, off);
            if (lane == 0)
                hidden[h] = fmaxf(acc + fc1_b[h], 0.f);
        }
    }
    __syncthreads();

    // ---- FC2
    if (tid < 10) {
        float acc = fc2_b[tid];
#pragma unroll 8
        for (int h = 0; h < 64; h++)
            acc += hidden[h] * fc2_w[tid * 64 + h];
        out[b * 10 + tid] = acc;
    }
}

extern "C" void kernel_launch(void* const* d_in, const int* in_sizes, int n_in,
                              void* d_out, int out_size) {
    const float* x     = (const float*)d_in[0];
    const float* w     = (const float*)d_in[1];
    const float* fc1_w = (const float*)d_in[2];
    const float* fc1_b = (const float*)d_in[3];
    const float* fc2_w = (const float*)d_in[4];
    const float* fc2_b = (const float*)d_in[5];
    float* out = (float*)d_out;

    const int B = in_sizes[0] / 784;  // 128
    qnet_kernel<<<B, THREADS>>>(x, w, fc1_w, fc1_b, fc2_w, fc2_b, out);
}

// round 14
// speedup vs baseline: 1.4636x; 1.4636x over previous
#include <cuda_runtime.h>

#define THREADS 896   // 28 warps; threads 0..783 = 196 patches x 4 sub-threads
#define NWARPS 28

typedef unsigned long long u64;

// ---- packed f32x2 primitives ----
__device__ __forceinline__ u64 pk2(float lo, float hi) {
    u64 r;
    asm("mov.b64 %0, {%1, %2};" : "=l"(r)
        : "r"(__float_as_uint(lo)), "r"(__float_as_uint(hi)));
    return r;
}
__device__ __forceinline__ void upk2(float& lo, float& hi, u64 v) {
    unsigned a, b;
    asm("mov.b64 {%0, %1}, %2;" : "=r"(a), "=r"(b) : "l"(v));
    lo = __uint_as_float(a); hi = __uint_as_float(b);
}
__device__ __forceinline__ u64 fma2_(u64 a, u64 b, u64 c) {
    u64 d;
    asm("fma.rn.f32x2 %0, %1, %2, %3;" : "=l"(d) : "l"(a), "l"(b), "l"(c));
    return d;
}
__device__ __forceinline__ u64 mul2_(u64 a, u64 b) {
    u64 d;
    asm("mul.rn.f32x2 %0, %1, %2;" : "=l"(d) : "l"(a), "l"(b));
    return d;
}
// swapped-half view and lo/hi mix — pure register renaming at SASS
__device__ __forceinline__ u64 swap2(u64 v) {
    float lo, hi; upk2(lo, hi, v); return pk2(hi, lo);
}
__device__ __forceinline__ u64 mixlh(u64 x, u64 y) {  // (lo of x, hi of y)
    float xl, xh, yl, yh; upk2(xl, xh, x); upk2(yl, yh, y); return pk2(xl, yh);
}

// Cross-register packed butterfly, 12 coeffs (same as R12):
// c = [aa bb nbb cc dd ndd ncc dd ndd aa nbb bb]
__device__ __forceinline__ void bfly12(u64 rA, u64 iA, u64 rB, u64 iB,
                                       const u64* c,
                                       u64& orA, u64& oiA, u64& orB, u64& oiB) {
    orA = fma2_(c[5],  iB, fma2_(c[3], rB, fma2_(c[2], iA, mul2_(c[0], rA))));
    oiA = fma2_(c[4],  rB, fma2_(c[3], iB, fma2_(c[1], rA, mul2_(c[0], iA))));
    orB = fma2_(c[11], iB, fma2_(c[9], rB, fma2_(c[8], iA, mul2_(c[6], rA))));
    oiB = fma2_(c[10], rB, fma2_(c[9], iB, fma2_(c[7], rA, mul2_(c[6], iA))));
}

__global__ __launch_bounds__(THREADS, 1)
void qnet_kernel(const float* __restrict__ x,       // [B,1,28,28]
                 const float* __restrict__ weight,  // [60]
                 const float* __restrict__ fc1_w,   // [64,784]
                 const float* __restrict__ fc1_b,   // [64]
                 const float* __restrict__ fc2_w,   // [10,64]
                 const float* __restrict__ fc2_b,   // [10]
                 float* __restrict__ out)           // [B,10]
{
    __shared__ __align__(16) float feat[784];
    __shared__ float  hidden[64];
    __shared__ float4 g[20];          // fused Ry*Rz*Ry per (layer,qubit)
    // Coefficient banks for layers 1..4 with ALL ring CNOTs folded in:
    __shared__ u64 cG0[4][2][6];      // intra-reg q0 gate (X30 pre-fold by r3): C1 C2 C3 C4 D1 D3
    __shared__ u64 cG1[4][12];        // cross-reg q1 bfly (X01 fold applied as half-mix in code)
    __shared__ u64 cG2[4][2][12];     // split q2 (row r2; X12 fold per register parity): 2x[aR aIN aI bR bIN bI]
    __shared__ u64 cG3[4][4][6];      // split q3 (row r3; X23 fold by r2): [aR aIN aI bR bIN bI]

    const int b   = blockIdx.x;
    const int tid = threadIdx.x;

    // ---- Stage 1: fused SU(2) gates U = Ry(p2)*Rz(p1)*Ry(p0)
    if (tid < 20) {
        const int L = tid >> 2, q = tid & 3;
        const float* p = weight + 12 * L;
        float ca, sa, cb, sb, cc, sc;
        sincosf(0.5f * p[q],     &sa, &ca);
        sincosf(0.5f * p[4 + q], &sb, &cb);
        sincosf(0.5f * p[8 + q], &sc, &cc);
        float t0 = cc * ca - sc * sa;
        float t1 = cc * ca + sc * sa;
        float t2 = cc * sa + sc * ca;
        float t3 = cc * sa - sc * ca;
        g[tid] = make_float4(cb * t0, -sb * t1, -cb * t2, sb * t3);
    }
    __syncthreads();

    // ---- Stage 2: coefficient banks
    if (tid < 8) {
        // cG0[li][r3]: q0 gate, X30(ring li) pre-fold = column swap when r3=1.
        // Generic 2x2 [[p+iq, r+is],[t+iu, v+iw]] -> intra-register 6-bank.
        const int li = tid >> 1, r3 = tid & 1;
        float4 G = g[(li + 1) * 4 + 0];
        float a = G.x, bb = G.y, c = G.z, d = G.w;
        float p, q, r, s, t, u, v, w;
        if (r3 == 0) { p = a; q = bb; r = c; s = d; t = -c; u = d;   v = a;  w = -bb; }
        else         { p = c; q = d;  r = a; s = bb; t = a; u = -bb; v = -c; w = d; }
        u64* o = cG0[li][r3];
        o[0] = pk2(p, v);    // C1 (on zr / zi)
        o[1] = pk2(-q, -w);  // C2 (on zi, re-chain)
        o[2] = pk2(r, t);    // C3 (on zsr; also on zsi in im-chain)
        o[3] = pk2(-s, -u);  // C4 (on zsi, re-chain)
        o[4] = pk2(q, w);    // D1 (on zr, im-chain)
        o[5] = pk2(s, u);    // D3 (on zsr, im-chain)
    } else if (tid < 12) {
        const int li = tid - 8;
        float4 G = g[(li + 1) * 4 + 1];
        float a = G.x, bb = G.y, c = G.z, d = G.w;
        u64* o = cG1[li];
        o[0] = pk2(a, a);    o[1]  = pk2(bb, bb);   o[2]  = pk2(-bb, -bb);
        o[3] = pk2(c, c);    o[4]  = pk2(d, d);     o[5]  = pk2(-d, -d);
        o[6] = pk2(-c, -c);  o[7]  = pk2(d, d);     o[8]  = pk2(-d, -d);
        o[9] = pk2(a, a);    o[10] = pk2(-bb, -bb); o[11] = pk2(bb, bb);
    } else if (tid < 20) {
        // cG2[li][r2]: split-q2 gate, own row rho=r2; X12(ring) fold: registers
        // with b1=1 (k=1) use opposite-row coeffs (only layers 1..3).
        const int idx = tid - 12, li = idx >> 1, r2 = idx & 1;
        float4 G = g[(li + 1) * 4 + 2];
        float a = G.x, bb = G.y, c = G.z, d = G.w;
        const bool rs = (li + 1) < 4;
        float a0r, a0i, b0r, b0i, a1r, a1i, b1r, b1i;
        if (r2 == 0) { a0r = a; a0i = bb;  b0r = c;  b0i = d; }
        else         { a0r = a; a0i = -bb; b0r = -c; b0i = d; }
        if (rs) {
            if (r2 == 0) { a1r = -c; a1i = d; b1r = a; b1i = -bb; }
            else         { a1r = c;  a1i = d; b1r = a; b1i = bb; }
        } else { a1r = a0r; a1i = a0i; b1r = b0r; b1i = b0i; }
        u64* o = cG2[li][r2];
        o[0] = pk2(a0r, a0r); o[1] = pk2(-a0i, -a0i); o[2] = pk2(a0i, a0i);
        o[3] = pk2(b0r, b0r); o[4] = pk2(-b0i, -b0i); o[5] = pk2(b0i, b0i);
        o[6] = pk2(a1r, a1r); o[7] = pk2(-a1i, -a1i); o[8] = pk2(a1i, a1i);
        o[9] = pk2(b1r, b1r); o[10] = pk2(-b1i, -b1i); o[11] = pk2(b1i, b1i);
    } else if (tid < 36) {
        // cG3[li][sub]: split-q3 gate, own row rho=r3; X23(ring) fold when r2=1
        // (layers 1..3 only).
        const int idx = tid - 20, li = idx >> 2, sub = idx & 3;
        const int r2 = sub >> 1, r3 = sub & 1;
        float4 G = g[(li + 1) * 4 + 3];
        float a = G.x, bb = G.y, c = G.z, d = G.w;
        const bool fold = ((li + 1) < 4) && r2;
        float ar_, ai_, br_, bi_;
        if (!fold) {
            if (r3 == 0) { ar_ = a;  ai_ = bb; br_ = c;  bi_ = d; }
            else         { ar_ = a;  ai_ = -bb; br_ = -c; bi_ = d; }
        } else {
            if (r3 == 0) { ar_ = -c; ai_ = d;  br_ = a;  bi_ = -bb; }
            else         { ar_ = c;  ai_ = d;  br_ = a;  bi_ = bb; }
        }
        u64* o = cG3[li][sub];
        o[0] = pk2(ar_, ar_); o[1] = pk2(-ai_, -ai_); o[2] = pk2(ai_, ai_);
        o[3] = pk2(br_, br_); o[4] = pk2(-bi_, -bi_); o[5] = pk2(bi_, bi_);
    }
    __syncthreads();

    // ---- Circuit: 4 threads per patch. Per-thread state: 4 amps [b0][b1],
    // pack lane = b0 (lo: b0=0), register k = b1. Lane bits: r2 = q2, r3 = q3.
    {
        const int p_raw = tid >> 2;
        const bool valid = p_raw < 196;
        const int p   = valid ? p_raw : 195;
        const int sub = tid & 3;
        const int r2  = sub >> 1;
        const int r3  = sub & 1;

        const int pi_ = p / 14, pj = p % 14;
        const float* xb = x + b * 784 + (2 * pi_) * 28 + 2 * pj;
        const float2 xr0 = *reinterpret_cast<const float2*>(xb);
        const float2 xr1 = *reinterpret_cast<const float2*>(xb + 28);
        const float ang[4] = { xr0.x, xr0.y, xr1.x, xr1.y };

        // Layer 0 fused with Rx encoding on |0000>; ring-0's X01,X12,X23 via
        // twisted product: amp[b0][b1] = A(b0)*B(b0^b1)*C(b1^r2)*D(r2^r3)
        const float PI = 3.14159265358979323846f;
        float R0[3], I0[3], R1[3], I1[3];
        float v3r, v3i;
        const int d3 = r2 ^ r3;
#pragma unroll
        for (int q = 0; q < 4; q++) {
            float sx, cx;
            __sincosf(PI * ang[q], &sx, &cx);
            float4 G = g[q];
            float a0r =  G.x * cx + G.w * sx;
            float a0i =  G.y * cx - G.z * sx;
            float a1r = -(G.z * cx + G.y * sx);
            float a1i =  G.w * cx - G.x * sx;
            if (q < 3) { R0[q] = a0r; I0[q] = a0i; R1[q] = a1r; I1[q] = a1i; }
            else       { v3r = d3 ? a1r : a0r; v3i = d3 ? a1i : a0i; }
        }

        u64 zr[2], zi[2];
        {
            // CD[b1] = C[b1 ^ r2] * D
            float cd_r[2], cd_i[2];
#pragma unroll
            for (int b1 = 0; b1 < 2; b1++) {
                int ic = b1 ^ r2;
                float cr = ic ? R1[2] : R0[2], ci = ic ? I1[2] : I0[2];
                cd_r[b1] = cr * v3r - ci * v3i;
                cd_i[b1] = cr * v3i + ci * v3r;
            }
            float ar_[2][2], ai_[2][2];   // amp[b0][b1]
#pragma unroll
            for (int b0 = 0; b0 < 2; b0++) {
                float Ar = b0 ? R1[0] : R0[0], Ai = b0 ? I1[0] : I0[0];
#pragma unroll
                for (int b1 = 0; b1 < 2; b1++) {
                    int ib = b0 ^ b1;
                    float Br = ib ? R1[1] : R0[1], Bi = ib ? I1[1] : I0[1];
                    float abr = Ar * Br - Ai * Bi;
                    float abi = Ar * Bi + Ai * Br;
                    ar_[b0][b1] = abr * cd_r[b1] - abi * cd_i[b1];
                    ai_[b0][b1] = abr * cd_i[b1] + abi * cd_r[b1];
                }
            }
            zr[0] = pk2(ar_[0][0], ar_[1][0]);  zi[0] = pk2(ai_[0][0], ai_[1][0]);
            zr[1] = pk2(ar_[0][1], ar_[1][1]);  zi[1] = pk2(ai_[0][1], ai_[1][1]);
        }

        // ---- Blocks 1..4
#pragma unroll
        for (int layer = 1; layer < 5; layer++) {
            const int li = layer - 1;
            const bool rs = (layer < 4);

            // G0' (q0 = pack lane, intra-register; X30 pre-fold in bank)
            {
                const u64* c = cG0[li][r3];
#pragma unroll
                for (int k = 0; k < 2; k++) {
                    u64 sr = swap2(zr[k]), si = swap2(zi[k]);
                    u64 nre = fma2_(c[3], si, fma2_(c[2], sr, fma2_(c[1], zi[k], mul2_(c[0], zr[k]))));
                    u64 nim = fma2_(c[2], si, fma2_(c[5], sr, fma2_(c[0], zi[k], mul2_(c[4], zr[k]))));
                    zr[k] = nre; zi[k] = nim;
                }
            }
            // G1' (q1 = register index, cross-register bfly; X01 fold = half-mix)
            {
                const u64* c = cG1[li];
                u64 nrA, niA, nrB, niB;
                bfly12(zr[0], zi[0], zr[1], zi[1], c, nrA, niA, nrB, niB);
                if (rs) {
                    zr[0] = mixlh(nrA, nrB); zi[0] = mixlh(niA, niB);
                    zr[1] = mixlh(nrB, nrA); zi[1] = mixlh(niB, niA);
                } else {
                    zr[0] = nrA; zi[0] = niA; zr[1] = nrB; zi[1] = niB;
                }
            }
            // G2' (split q2, xor 2; X12 fold per register parity in bank)
            {
                const u64* o = cG2[li][r2];
#pragma unroll
                for (int k = 0; k < 2; k++) {
                    const u64* c = o + 6 * k;
                    u64 pr = __shfl_xor_sync(0xffffffffu, zr[k], 2);
                    u64 pi = __shfl_xor_sync(0xffffffffu, zi[k], 2);
                    u64 nre = fma2_(c[4], pi, fma2_(c[3], pr, fma2_(c[1], zi[k], mul2_(c[0], zr[k]))));
                    u64 nim = fma2_(c[5], pr, fma2_(c[3], pi, fma2_(c[2], zr[k], mul2_(c[0], zi[k]))));
                    zr[k] = nre; zi[k] = nim;
                }
            }
            // G3' (split q3, xor 1; X23 fold by r2 in bank)
            {
                const u64* c = cG3[li][sub];
#pragma unroll
                for (int k = 0; k < 2; k++) {
                    u64 pr = __shfl_xor_sync(0xffffffffu, zr[k], 1);
                    u64 pi = __shfl_xor_sync(0xffffffffu, zi[k], 1);
                    u64 nre = fma2_(c[4], pi, fma2_(c[3], pr, fma2_(c[1], zi[k], mul2_(c[0], zr[k]))));
                    u64 nim = fma2_(c[5], pr, fma2_(c[3], pi, fma2_(c[2], zr[k], mul2_(c[0], zi[k]))));
                    zr[k] = nre; zi[k] = nim;
                }
            }
        }

        // ---- <Z_q> partials + quad reduction
        u64 s0 = fma2_(zr[0], zr[0], mul2_(zi[0], zi[0]));
        u64 s1 = fma2_(zr[1], zr[1], mul2_(zi[1], zi[1]));
        float pe0, po0, pe1, po1;
        upk2(pe0, po0, s0);   // (b0=0,b1=0), (b0=1,b1=0)
        upk2(pe1, po1, s1);   // (b0=0,b1=1), (b0=1,b1=1)
        float S  = pe0 + po0 + pe1 + po1;
        float e0 = (pe0 + pe1) - (po0 + po1);   // q0 sign by b0
        float e1 = (pe0 + po0) - (pe1 + po1);   // q1 sign by b1
        float e2 = r2 ? -S : S;
        float e3 = r3 ? -S : S;
#pragma unroll
        for (int off = 1; off <= 2; off <<= 1) {
            e0 += __shfl_xor_sync(0xffffffffu, e0, off);
            e1 += __shfl_xor_sync(0xffffffffu, e1, off);
            e2 += __shfl_xor_sync(0xffffffffu, e2, off);
            e3 += __shfl_xor_sync(0xffffffffu, e3, off);
        }
        if (valid) {
            float val = (sub == 0) ? e0 : (sub == 1) ? e1 : (sub == 2) ? e2 : e3;
            feat[p * 4 + sub] = val;
        }
    }
    __syncthreads();

    // ---- FC1 (packed): hidden[h] = relu(feat . fc1_w[h,:] + fc1_b[h])
    {
        const int warp = tid >> 5;
        const int lane = tid & 31;
        const u64* F2 = reinterpret_cast<const u64*>(feat);
        for (int h = warp; h < 64; h += NWARPS) {
            u64 acc2 = 0ull;
            for (int kk = lane; kk < 196; kk += 32) {
                const ulonglong2 wv =
                    *reinterpret_cast<const ulonglong2*>(fc1_w + (h * 196 + kk) * 4);
                acc2 = fma2_(wv.x, F2[2 * kk],     acc2);
                acc2 = fma2_(wv.y, F2[2 * kk + 1], acc2);
            }
            float alo, ahi;
            upk2(alo, ahi, acc2);
            float acc = alo + ahi;
#pragma unroll
            for (int off = 16; off; off >>= 1)
                acc += __shfl_down_sync(0xffffffffu, acc, off);
            if (lane == 0)
                hidden[h] = fmaxf(acc + fc1_b[h], 0.f);
        }
    }
    __syncthreads();

    // ---- FC2
    if (tid < 10) {
        float acc = fc2_b[tid];
#pragma unroll 8
        for (int h = 0; h < 64; h++)
            acc += hidden[h] * fc2_w[tid * 64 + h];
        out[b * 10 + tid] = acc;
    }
}

extern "C" void kernel_launch(void* const* d_in, const int* in_sizes, int n_in,
                              void* d_out, int out_size) {
    const float* x     = (const float*)d_in[0];
    const float* w     = (const float*)d_in[1];
    const float* fc1_w = (const float*)d_in[2];
    const float* fc1_b = (const float*)d_in[3];
    const float* fc2_w = (const float*)d_in[4];
    const float* fc2_b = (const float*)d_in[5];
    float* out = (float*)d_out;

    const int B = in_sizes[0] / 784;  // 128
    qnet_kernel<<<B, THREADS>>>(x, w, fc1_w, fc1_b, fc2_w, fc2_b, out);
}